// round 13
// baseline (speedup 1.0000x reference)
#include <cuda_runtime.h>
#include <cstdint>

// ---------------------------------------------------------------------------
// TGN layer-graph sum embedding, fused per layer. Round 13 (= R12 resubmit;
// R12 bench died at GB300 container acquisition — broker infra, kernel never
// compiled/ran. Audit: no hang path; warp-uniform continue, full-mask shfl,
// matched wait_groups, chunk-lockstep smem ordering. Same structure as R11
// which ran.)
// vs R11 (473us, latency-bound: tensor 17.7%, alu 16.7%, nothing saturated):
//  1. tf32 conversion moved to PRODUCERS: agg/h/reload values converted once
//     when written to smem -> A-fragment loads are plain LDS; kills 8 of 16
//     cvts per k8 per thread. Numerically IDENTICAL (same rna rounding).
//  2. edge/time sums: lane remap (c4 = lane&7 float4-col, rg = lane>>3 row
//     group) -> 8 LDG.128 + 16 shfl per node-warp instead of 32 LDG.32
//     (4x fewer L1 wavefronts + issue slots on the 819MB/layer DRAM stream).
// GEMM core, pipeline, layout (PA_=196, PW_=136, CH=16) unchanged from R11.
// ---------------------------------------------------------------------------

#define DD   128
#define KK   16
#define DE   32
#define DT   32
#define D1   192
#define TB   64
#define PA_  196           // A pitch (floats), 196 % 32 == 4
#define PW_  136           // staged-W pitch, 136 % 32 == 8
#define CH   16            // W chunk rows
#define NMAX 100000

__device__ float g_buf[(size_t)NMAX * DD];

__device__ __forceinline__ uint32_t f2tf(float x) {
    uint32_t r; asm("cvt.rna.tf32.f32 %0, %1;" : "=r"(r) : "f"(x)); return r;
}
__device__ __forceinline__ float f2tf_f(float x) {
    return __uint_as_float(f2tf(x));
}
__device__ __forceinline__ void mma_tf32(float d[4], const uint32_t a[4], const uint32_t b[2]) {
    asm volatile(
        "mma.sync.aligned.m16n8k8.row.col.f32.tf32.tf32.f32 "
        "{%0,%1,%2,%3}, {%4,%5,%6,%7}, {%8,%9}, {%0,%1,%2,%3};"
        : "+f"(d[0]), "+f"(d[1]), "+f"(d[2]), "+f"(d[3])
        : "r"(a[0]), "r"(a[1]), "r"(a[2]), "r"(a[3]), "r"(b[0]), "r"(b[1]));
}
__device__ __forceinline__ void cpa16(uint32_t dst, const void* src) {
    asm volatile("cp.async.cg.shared.global [%0], [%1], 16;" :: "r"(dst), "l"(src));
}
__device__ __forceinline__ void cp_commit() { asm volatile("cp.async.commit_group;"); }
__device__ __forceinline__ void cp_wait0()  { asm volatile("cp.async.wait_group 0;"); }

// stage W chunk (16 rows x 128 cols, global row-major) into Ws[buf] pitch PW_
__device__ __forceinline__ void issue_chunk(uint32_t wsa, int buf,
                                            const float* Wg, int chunk, int tid) {
    const float4* s = (const float4*)(Wg + (size_t)chunk * CH * DD);
    uint32_t d = wsa + (uint32_t)buf * (CH * PW_ * 4);
    {
        int f = tid;              // float4 index 0..511
        int r = f >> 5, c = f & 31;
        cpa16(d + (uint32_t)(r * PW_ + c * 4) * 4, s + f);
    }
    {
        int f = tid + 256;
        int r = f >> 5, c = f & 31;
        cpa16(d + (uint32_t)(r * PW_ + c * 4) * 4, s + f);
    }
    cp_commit();
}

// acc[2 m-tiles][4 n-tiles][4] += A(64 x nCh*16, smem pitch PA_, already tf32)
// @ W(nCh*16 x 128). Warp (mh,nq) owns rows [32mh,+32) x cols [32nq,+32).
// If pre==true, chunk 0 already issued. No trailing barrier (caller syncs).
__device__ __forceinline__ void gemm_mma(
    const float* __restrict__ Ag,
    const float* __restrict__ Wg,
    const float* __restrict__ Ws, uint32_t wsa,
    int nCh, float acc[2][4][4],
    int mh, int nq, int gid, int tig, int tid, bool pre)
{
    if (!pre) issue_chunk(wsa, 0, Wg, 0, tid);
    for (int c = 0; c < nCh; c++) {
        cp_wait0();
        __syncthreads();          // chunk c visible; prior-buf reads done
        if (c + 1 < nCh) issue_chunk(wsa, (c + 1) & 1, Wg, c + 1, tid);

        const float* wbase = Ws + (c & 1) * (CH * PW_);
        #pragma unroll
        for (int k8 = 0; k8 < 2; k8++) {
            const float* ap0 = Ag + (32 * mh + gid) * PA_ + c * CH + k8 * 8 + tig;
            uint32_t af[2][4];
            #pragma unroll
            for (int mi = 0; mi < 2; mi++) {
                const float* ap = ap0 + mi * 16 * PA_;
                af[mi][0] = __float_as_uint(ap[0]);           // pre-converted tf32
                af[mi][1] = __float_as_uint(ap[8 * PA_]);
                af[mi][2] = __float_as_uint(ap[4]);
                af[mi][3] = __float_as_uint(ap[8 * PA_ + 4]);
            }
            const float* wp = wbase + (k8 * 8 + tig) * PW_ + 32 * nq + gid;
            uint32_t bf[4][2];
            #pragma unroll
            for (int ni = 0; ni < 4; ni++) {
                bf[ni][0] = f2tf(wp[8 * ni]);
                bf[ni][1] = f2tf(wp[4 * PW_ + 8 * ni]);
            }
            #pragma unroll
            for (int mi = 0; mi < 2; mi++)
                #pragma unroll
                for (int ni = 0; ni < 4; ni++)
                    mma_tf32(acc[mi][ni], af[mi], bf[ni]);
        }
    }
}

extern "C" __global__ void __launch_bounds__(256, 3)
tgn_layer(const float* __restrict__ src,
          const float* __restrict__ e,
          const float* __restrict__ t,
          const float* __restrict__ W1g,
          const float* __restrict__ b1g,
          const float* __restrict__ W2g,
          const float* __restrict__ b2g,
          const void* __restrict__ idxRaw,
          int layer,
          float* __restrict__ dst,
          int N)
{
    extern __shared__ float sm[];
    float* agg = sm;                  // [64][PA_] row-major tf32; cols 0..127 reused
    float* Ws  = agg + TB * PA_;      // [2][CH*PW_] double buffer (fp32)
    __shared__ int s_flag;

    const int tid  = threadIdx.x;
    const int lane = tid & 31;
    const int w    = tid >> 5;
    const int gid  = lane >> 2;       // 0..7
    const int tig  = lane & 3;        // 0..3
    const int mh   = w & 1;
    const int nq   = w >> 1;
    const int c4   = lane & 7;        // float4 col group for e/t
    const int rg   = lane >> 3;       // row group 0..3 for e/t
    const int base = blockIdx.x * TB;
    const uint32_t wsa = (uint32_t)__cvta_generic_to_shared(Ws);

    // prefetch W1 chunk 0 under phase A
    issue_chunk(wsa, 0, W1g, 0, tid);

    // idx dtype detection (int64 values < 1e5 -> every odd 32-bit word == 0)
    if (tid == 0) s_flag = 0;
    __syncthreads();
    if (tid < 64) {
        int v = ((const int*)idxRaw)[2 * tid + 1];
        if (v != 0) atomicOr(&s_flag, 1);
    }
    __syncthreads();
    const int idx64 = (s_flag == 0);

    const long long* i64 = (const long long*)idxRaw + (size_t)layer * N * KK;
    const int*       i32 = (const int*)idxRaw       + (size_t)layer * N * KK;

    // ---------------- Phase A: aggregation -> row-major tf32 smem -----------
    #pragma unroll 1
    for (int i = 0; i < 8; i++) {
        int ln = w * 8 + i;
        int n  = base + ln;
        if (n >= N) continue;     // warp-uniform (ln depends on w,i only)
        float4 accA = {0.f,0.f,0.f,0.f}, accB = {0.f,0.f,0.f,0.f};

        #pragma unroll
        for (int jj = 0; jj < 4; jj++) {
            long long q0, q1, q2, q3;
            if (idx64) {
                const long long* p = i64 + (size_t)n * KK + jj * 4;
                q0 = p[0]; q1 = p[1]; q2 = p[2]; q3 = p[3];
            } else {
                int4 v = ((const int4*)(i32 + (size_t)n * KK))[jj];
                q0 = v.x; q1 = v.y; q2 = v.z; q3 = v.w;
            }
            float4 v0 = ((const float4*)(src + (size_t)q0 * DD))[lane];
            float4 v1 = ((const float4*)(src + (size_t)q1 * DD))[lane];
            float4 v2 = ((const float4*)(src + (size_t)q2 * DD))[lane];
            float4 v3 = ((const float4*)(src + (size_t)q3 * DD))[lane];
            accA.x += v0.x; accA.y += v0.y; accA.z += v0.z; accA.w += v0.w;
            accB.x += v1.x; accB.y += v1.y; accB.z += v1.z; accB.w += v1.w;
            accA.x += v2.x; accA.y += v2.y; accA.z += v2.z; accA.w += v2.w;
            accB.x += v3.x; accB.y += v3.y; accB.z += v3.z; accB.w += v3.w;
        }
        accA.x += accB.x; accA.y += accB.y; accA.z += accB.z; accA.w += accB.w;

        // edge/time sums: [16][32] block, lane (rg, c4) loads 4 float4 rows
        const float4* e4 = (const float4*)(e + (size_t)n * (KK * DE));
        const float4* t4 = (const float4*)(t + (size_t)n * (KK * DT));
        float4 se = {0.f,0.f,0.f,0.f}, st = {0.f,0.f,0.f,0.f};
        #pragma unroll
        for (int r = 0; r < 4; r++) {
            int row = rg * 4 + r;
            float4 ev = e4[row * 8 + c4];
            float4 tv = t4[row * 8 + c4];
            se.x += ev.x; se.y += ev.y; se.z += ev.z; se.w += ev.w;
            st.x += tv.x; st.y += tv.y; st.z += tv.z; st.w += tv.w;
        }
        #pragma unroll
        for (int d = 8; d <= 16; d <<= 1) {
            se.x += __shfl_xor_sync(0xffffffffu, se.x, d);
            se.y += __shfl_xor_sync(0xffffffffu, se.y, d);
            se.z += __shfl_xor_sync(0xffffffffu, se.z, d);
            se.w += __shfl_xor_sync(0xffffffffu, se.w, d);
            st.x += __shfl_xor_sync(0xffffffffu, st.x, d);
            st.y += __shfl_xor_sync(0xffffffffu, st.y, d);
            st.z += __shfl_xor_sync(0xffffffffu, st.z, d);
            st.w += __shfl_xor_sync(0xffffffffu, st.w, d);
        }

        // producer-side tf32 conversion (same rna rounding as converting at load)
        float4 ca = { f2tf_f(accA.x), f2tf_f(accA.y), f2tf_f(accA.z), f2tf_f(accA.w) };
        *(float4*)&agg[ln * PA_ + 4 * lane] = ca;
        if (rg == 0) {
            float4 ce = { f2tf_f(se.x), f2tf_f(se.y), f2tf_f(se.z), f2tf_f(se.w) };
            float4 ct = { f2tf_f(st.x), f2tf_f(st.y), f2tf_f(st.z), f2tf_f(st.w) };
            *(float4*)&agg[ln * PA_ + DD + 4 * c4]      = ce;
            *(float4*)&agg[ln * PA_ + DD + DE + 4 * c4] = ct;
        }
    }
    __syncthreads();

    // ---------------- Phase B: h = relu(agg @ W1 + b1) ----------------------
    float acc[2][4][4];
    #pragma unroll
    for (int mi = 0; mi < 2; mi++)
        #pragma unroll
        for (int ni = 0; ni < 4; ni++)
            #pragma unroll
            for (int q = 0; q < 4; q++) acc[mi][ni][q] = 0.f;

    gemm_mma(agg, W1g, Ws, wsa, D1 / CH, acc, mh, nq, gid, tig, tid, true);

    // h -> agg cols [0,128), tf32-converted at producer. Safe: GEMM1's last
    // chunk reads cols 176..191 only; cols 0..175 reads precede its barrier.
    #pragma unroll
    for (int mi = 0; mi < 2; mi++)
        #pragma unroll
        for (int ni = 0; ni < 4; ni++) {
            int row = 32 * mh + 16 * mi + gid;
            int col = 32 * nq + 8 * ni + 2 * tig;
            float bv0 = b1g[col], bv1 = b1g[col + 1];
            float2 lo = { f2tf_f(fmaxf(acc[mi][ni][0] + bv0, 0.f)),
                          f2tf_f(fmaxf(acc[mi][ni][1] + bv1, 0.f)) };
            float2 hi = { f2tf_f(fmaxf(acc[mi][ni][2] + bv0, 0.f)),
                          f2tf_f(fmaxf(acc[mi][ni][3] + bv1, 0.f)) };
            *(float2*)&agg[row * PA_ + col]       = lo;
            *(float2*)&agg[(row + 8) * PA_ + col] = hi;
            #pragma unroll
            for (int q = 0; q < 4; q++) acc[mi][ni][q] = 0.f;
        }
    __syncthreads();   // all h visible before C1 reads

    // ---------------- Phase C1: acc += h @ W2[128:256] ----------------------
    gemm_mma(agg, W2g + DD * DD, Ws, wsa, DD / CH, acc, mh, nq, gid, tig, tid, false);
    __syncthreads();   // C1 reads of cols 0..127 done before reload overwrites

    // ---------------- reload own rows (L2-hot) into agg cols 0..127 ---------
    {
        const float4* cp4 = (const float4*)(src + (size_t)base * DD);
        #pragma unroll
        for (int i = 0; i < 8; i++) {
            int f  = tid + 256 * i;      // 0..2047
            int n  = f >> 5;             // node 0..63
            int k4 = f & 31;
            if (base + n < N) {
                float4 v = cp4[f];
                float4 cv = { f2tf_f(v.x), f2tf_f(v.y), f2tf_f(v.z), f2tf_f(v.w) };
                *(float4*)&agg[n * PA_ + 4 * k4] = cv;
            }
        }
    }
    // ordering to C2's LDS: C2's chunk-0 wait+__syncthreads (BAR drains STS)

    // ---------------- Phase C2: acc += cur @ W2[0:128] ----------------------
    gemm_mma(agg, W2g, Ws, wsa, DD / CH, acc, mh, nq, gid, tig, tid, false);

    #pragma unroll
    for (int mi = 0; mi < 2; mi++)
        #pragma unroll
        for (int ni = 0; ni < 4; ni++) {
            int row = 32 * mh + 16 * mi + gid;
            int col = 32 * nq + 8 * ni + 2 * tig;
            float bv0 = b2g[col], bv1 = b2g[col + 1];
            int n1 = base + row, n2 = base + row + 8;
            if (n1 < N) {
                float2 o = { acc[mi][ni][0] + bv0, acc[mi][ni][1] + bv1 };
                *(float2*)&dst[(size_t)n1 * DD + col] = o;
            }
            if (n2 < N) {
                float2 o = { acc[mi][ni][2] + bv0, acc[mi][ni][3] + bv1 };
                *(float2*)&dst[(size_t)n2 * DD + col] = o;
            }
        }
}

extern "C" void kernel_launch(void* const* d_in, const int* in_sizes, int n_in,
                              void* d_out, int out_size)
{
    const float* features = (const float*)d_in[0];
    const float* edge     = (const float*)d_in[1];
    const float* timef    = (const float*)d_in[2];
    const float* W1       = (const float*)d_in[3];
    const float* b1       = (const float*)d_in[4];
    const float* W2       = (const float*)d_in[5];
    const float* b2       = (const float*)d_in[6];
    const void*  idx      = d_in[7];
    float*       out      = (float*)d_out;

    const int N = in_sizes[0] / DD;

    const size_t smem = (size_t)(TB * PA_ + 2 * CH * PW_) * sizeof(float); // 67,584 B
    cudaFuncSetAttribute(tgn_layer, cudaFuncAttributeMaxDynamicSharedMemorySize, (int)smem);

    void* gptr = nullptr;
    cudaGetSymbolAddress(&gptr, g_buf);
    float* gbuf = (float*)gptr;

    const int blocks = (N + TB - 1) / TB;
    const size_t eoff = (size_t)N * KK * DE;
    const size_t toff = (size_t)N * KK * DT;

    tgn_layer<<<blocks, 256, smem>>>(features, edge, timef,
                                     W1, b1, W2, b2, idx, 0, gbuf, N);
    tgn_layer<<<blocks, 256, smem>>>(gbuf, edge + eoff, timef + toff,
                                     W1 + D1 * DD, b1 + DD,
                                     W2 + 2 * DD * DD, b2 + DD,
                                     idx, 1, out, N);
}

// round 15
// speedup vs baseline: 1.0572x; 1.0572x over previous
#include <cuda_runtime.h>
#include <cstdint>

// ---------------------------------------------------------------------------
// TGN layer-graph sum embedding, fused per layer. Round 15 (= R14 resubmit;
// R14 bench died at GB300 container acquisition — broker infra failure #7,
// kernel never compiled/ran. Audit: uniform barriers, matched wait_groups,
// occupancy arithmetic valid; strict structural shrink of R11 which ran.)
// R13 post-mortem: producer-cvt + shfl e/t were net-negative (alu unchanged ->
// alu = gather address math, not cvt). Reverted to R11 phase A / epilogues.
// R11/R13 profiles: NOTHING saturated (tensor 17, L1 45-48, DRAM 34, issue 31,
// occ 35.6) -> latency*concurrency bound, occupancy capped at 3 CTAs by
// smem 67.6KB + regs 80.
// R14/R15 change: TB 64 -> 32. smem 42.5KB, acc 32->16 regs,
// launch_bounds(256,4) -> 4 CTAs/SM (32 warps, +33% concurrency, 4
// independent barrier domains). Warp tile: 16 rows x 32 cols. GEMM pipeline
// (PA_=196, PW_=136, CH=16, double-buffered cp.async) unchanged.
// ---------------------------------------------------------------------------

#define DD   128
#define KK   16
#define DE   32
#define DT   32
#define D1   192
#define TB   32
#define PA_  196           // A pitch (floats), 196 % 32 == 4
#define PW_  136           // staged-W pitch, 136 % 32 == 8
#define CH   16            // W chunk rows
#define NMAX 100000

__device__ float g_buf[(size_t)NMAX * DD];

__device__ __forceinline__ uint32_t f2tf(float x) {
    uint32_t r; asm("cvt.rna.tf32.f32 %0, %1;" : "=r"(r) : "f"(x)); return r;
}
__device__ __forceinline__ void mma_tf32(float d[4], const uint32_t a[4], const uint32_t b[2]) {
    asm volatile(
        "mma.sync.aligned.m16n8k8.row.col.f32.tf32.tf32.f32 "
        "{%0,%1,%2,%3}, {%4,%5,%6,%7}, {%8,%9}, {%0,%1,%2,%3};"
        : "+f"(d[0]), "+f"(d[1]), "+f"(d[2]), "+f"(d[3])
        : "r"(a[0]), "r"(a[1]), "r"(a[2]), "r"(a[3]), "r"(b[0]), "r"(b[1]));
}
__device__ __forceinline__ void cpa16(uint32_t dst, const void* src) {
    asm volatile("cp.async.cg.shared.global [%0], [%1], 16;" :: "r"(dst), "l"(src));
}
__device__ __forceinline__ void cp_commit() { asm volatile("cp.async.commit_group;"); }
__device__ __forceinline__ void cp_wait0()  { asm volatile("cp.async.wait_group 0;"); }

// stage W chunk (16 rows x 128 cols, global row-major) into Ws[buf] pitch PW_
__device__ __forceinline__ void issue_chunk(uint32_t wsa, int buf,
                                            const float* Wg, int chunk, int tid) {
    const float4* s = (const float4*)(Wg + (size_t)chunk * CH * DD);
    uint32_t d = wsa + (uint32_t)buf * (CH * PW_ * 4);
    {
        int f = tid;              // float4 index 0..511
        int r = f >> 5, c = f & 31;
        cpa16(d + (uint32_t)(r * PW_ + c * 4) * 4, s + f);
    }
    {
        int f = tid + 256;
        int r = f >> 5, c = f & 31;
        cpa16(d + (uint32_t)(r * PW_ + c * 4) * 4, s + f);
    }
    cp_commit();
}

// acc[4 n-tiles][4] += A(32 x nCh*16, smem pitch PA_) @ W(nCh*16 x 128).
// Warp (mh,nq) owns rows [16mh,+16) x cols [32nq,+32).
// If pre==true, chunk 0 already issued. No trailing barrier (caller syncs).
__device__ __forceinline__ void gemm_mma(
    const float* __restrict__ Ag,
    const float* __restrict__ Wg,
    const float* __restrict__ Ws, uint32_t wsa,
    int nCh, float acc[4][4],
    int mh, int nq, int gid, int tig, int tid, bool pre)
{
    if (!pre) issue_chunk(wsa, 0, Wg, 0, tid);
    for (int c = 0; c < nCh; c++) {
        cp_wait0();
        __syncthreads();          // chunk c visible; prior-buf reads done
        if (c + 1 < nCh) issue_chunk(wsa, (c + 1) & 1, Wg, c + 1, tid);

        const float* wbase = Ws + (c & 1) * (CH * PW_);
        #pragma unroll
        for (int k8 = 0; k8 < 2; k8++) {
            const float* ap = Ag + (16 * mh + gid) * PA_ + c * CH + k8 * 8 + tig;
            uint32_t af[4];
            af[0] = f2tf(ap[0]);
            af[1] = f2tf(ap[8 * PA_]);
            af[2] = f2tf(ap[4]);
            af[3] = f2tf(ap[8 * PA_ + 4]);

            const float* wp = wbase + (k8 * 8 + tig) * PW_ + 32 * nq + gid;
            uint32_t bf[4][2];
            #pragma unroll
            for (int ni = 0; ni < 4; ni++) {
                bf[ni][0] = f2tf(wp[8 * ni]);
                bf[ni][1] = f2tf(wp[4 * PW_ + 8 * ni]);
            }
            #pragma unroll
            for (int ni = 0; ni < 4; ni++)
                mma_tf32(acc[ni], af, bf[ni]);
        }
    }
}

extern "C" __global__ void __launch_bounds__(256, 4)
tgn_layer(const float* __restrict__ src,
          const float* __restrict__ e,
          const float* __restrict__ t,
          const float* __restrict__ W1g,
          const float* __restrict__ b1g,
          const float* __restrict__ W2g,
          const float* __restrict__ b2g,
          const void* __restrict__ idxRaw,
          int layer,
          float* __restrict__ dst,
          int N)
{
    extern __shared__ float sm[];
    float* agg = sm;                  // [32][PA_] row-major; cols 0..127 reused
    float* Ws  = agg + TB * PA_;      // [2][CH*PW_] double buffer
    __shared__ int s_flag;

    const int tid  = threadIdx.x;
    const int lane = tid & 31;
    const int w    = tid >> 5;
    const int gid  = lane >> 2;       // 0..7
    const int tig  = lane & 3;        // 0..3
    const int mh   = w & 1;           // m-tile (rows 16*mh..)
    const int nq   = w >> 1;          // n-quarter (cols 32*nq..)
    const int base = blockIdx.x * TB;
    const uint32_t wsa = (uint32_t)__cvta_generic_to_shared(Ws);

    // prefetch W1 chunk 0 under phase A
    issue_chunk(wsa, 0, W1g, 0, tid);

    // idx dtype detection (int64 values < 1e5 -> every odd 32-bit word == 0)
    if (tid == 0) s_flag = 0;
    __syncthreads();
    if (tid < 64) {
        int v = ((const int*)idxRaw)[2 * tid + 1];
        if (v != 0) atomicOr(&s_flag, 1);
    }
    __syncthreads();
    const int idx64 = (s_flag == 0);

    const long long* i64 = (const long long*)idxRaw + (size_t)layer * N * KK;
    const int*       i32 = (const int*)idxRaw       + (size_t)layer * N * KK;

    // ---------------- Phase A: aggregation -> row-major smem ----------------
    #pragma unroll 1
    for (int i = 0; i < 4; i++) {
        int ln = w * 4 + i;
        int n  = base + ln;
        if (n >= N) continue;     // warp-uniform (ln depends on w,i only)
        float4 accA = {0.f,0.f,0.f,0.f}, accB = {0.f,0.f,0.f,0.f};
        float es = 0.f, ts = 0.f;

        #pragma unroll
        for (int jj = 0; jj < 4; jj++) {
            long long q0, q1, q2, q3;
            if (idx64) {
                const long long* p = i64 + (size_t)n * KK + jj * 4;
                q0 = p[0]; q1 = p[1]; q2 = p[2]; q3 = p[3];
            } else {
                int4 v = ((const int4*)(i32 + (size_t)n * KK))[jj];
                q0 = v.x; q1 = v.y; q2 = v.z; q3 = v.w;
            }
            float4 v0 = ((const float4*)(src + (size_t)q0 * DD))[lane];
            float4 v1 = ((const float4*)(src + (size_t)q1 * DD))[lane];
            float4 v2 = ((const float4*)(src + (size_t)q2 * DD))[lane];
            float4 v3 = ((const float4*)(src + (size_t)q3 * DD))[lane];
            accA.x += v0.x; accA.y += v0.y; accA.z += v0.z; accA.w += v0.w;
            accB.x += v1.x; accB.y += v1.y; accB.z += v1.z; accB.w += v1.w;
            accA.x += v2.x; accA.y += v2.y; accA.z += v2.z; accA.w += v2.w;
            accB.x += v3.x; accB.y += v3.y; accB.z += v3.z; accB.w += v3.w;
        }
        const float* ep = e + (size_t)n * (KK * DE);
        const float* tp = t + (size_t)n * (KK * DT);
        #pragma unroll
        for (int j = 0; j < KK; j++) {
            es += ep[j * DE + lane];
            ts += tp[j * DT + lane];
        }
        accA.x += accB.x; accA.y += accB.y; accA.z += accB.z; accA.w += accB.w;

        *(float4*)&agg[ln * PA_ + 4 * lane] = accA;   // conflict-free STS.128
        agg[ln * PA_ + DD + lane]      = es;
        agg[ln * PA_ + DD + DE + lane] = ts;
    }
    __syncthreads();

    // ---------------- Phase B: h = relu(agg @ W1 + b1) ----------------------
    float acc[4][4];
    #pragma unroll
    for (int ni = 0; ni < 4; ni++)
        #pragma unroll
        for (int q = 0; q < 4; q++) acc[ni][q] = 0.f;

    gemm_mma(agg, W1g, Ws, wsa, D1 / CH, acc, mh, nq, gid, tig, tid, true);

    // h -> agg cols [0,128). Safe: GEMM1's last chunk reads cols 176..191
    // only; reads of cols 0..175 precede its in-gemm barrier (chunk lockstep).
    #pragma unroll
    for (int ni = 0; ni < 4; ni++) {
        int row = 16 * mh + gid;
        int col = 32 * nq + 8 * ni + 2 * tig;
        float bv0 = b1g[col], bv1 = b1g[col + 1];
        float2 lo = { fmaxf(acc[ni][0] + bv0, 0.f),
                      fmaxf(acc[ni][1] + bv1, 0.f) };
        float2 hi = { fmaxf(acc[ni][2] + bv0, 0.f),
                      fmaxf(acc[ni][3] + bv1, 0.f) };
        *(float2*)&agg[row * PA_ + col]       = lo;
        *(float2*)&agg[(row + 8) * PA_ + col] = hi;
        #pragma unroll
        for (int q = 0; q < 4; q++) acc[ni][q] = 0.f;
    }
    __syncthreads();   // all h visible before C1 reads

    // ---------------- Phase C1: acc += h @ W2[128:256] ----------------------
    gemm_mma(agg, W2g + DD * DD, Ws, wsa, DD / CH, acc, mh, nq, gid, tig, tid, false);
    __syncthreads();   // C1 reads of cols 0..127 done before reload overwrites

    // ---------------- reload own rows (L2-hot) into agg cols 0..127 ---------
    {
        const float4* cp4 = (const float4*)(src + (size_t)base * DD);
        #pragma unroll
        for (int i = 0; i < 4; i++) {
            int f  = tid + 256 * i;      // 0..1023
            int n  = f >> 5;             // node 0..31
            int k4 = f & 31;
            if (base + n < N)
                *(float4*)&agg[n * PA_ + 4 * k4] = cp4[f];
        }
    }
    // ordering to C2's LDS: C2's chunk-0 wait+__syncthreads (BAR drains STS)

    // ---------------- Phase C2: acc += cur @ W2[0:128] ----------------------
    gemm_mma(agg, W2g, Ws, wsa, DD / CH, acc, mh, nq, gid, tig, tid, false);

    #pragma unroll
    for (int ni = 0; ni < 4; ni++) {
        int row = 16 * mh + gid;
        int col = 32 * nq + 8 * ni + 2 * tig;
        float bv0 = b2g[col], bv1 = b2g[col + 1];
        int n1 = base + row, n2 = base + row + 8;
        if (n1 < N) {
            float2 o = { acc[ni][0] + bv0, acc[ni][1] + bv1 };
            *(float2*)&dst[(size_t)n1 * DD + col] = o;
        }
        if (n2 < N) {
            float2 o = { acc[ni][2] + bv0, acc[ni][3] + bv1 };
            *(float2*)&dst[(size_t)n2 * DD + col] = o;
        }
    }
}

extern "C" void kernel_launch(void* const* d_in, const int* in_sizes, int n_in,
                              void* d_out, int out_size)
{
    const float* features = (const float*)d_in[0];
    const float* edge     = (const float*)d_in[1];
    const float* timef    = (const float*)d_in[2];
    const float* W1       = (const float*)d_in[3];
    const float* b1       = (const float*)d_in[4];
    const float* W2       = (const float*)d_in[5];
    const float* b2       = (const float*)d_in[6];
    const void*  idx      = d_in[7];
    float*       out      = (float*)d_out;

    const int N = in_sizes[0] / DD;

    const size_t smem = (size_t)(TB * PA_ + 2 * CH * PW_) * sizeof(float); // 42,496 B
    cudaFuncSetAttribute(tgn_layer, cudaFuncAttributeMaxDynamicSharedMemorySize, (int)smem);

    void* gptr = nullptr;
    cudaGetSymbolAddress(&gptr, g_buf);
    float* gbuf = (float*)gptr;

    const int blocks = (N + TB - 1) / TB;
    const size_t eoff = (size_t)N * KK * DE;
    const size_t toff = (size_t)N * KK * DT;

    tgn_layer<<<blocks, 256, smem>>>(features, edge, timef,
                                     W1, b1, W2, b2, idx, 0, gbuf, N);
    tgn_layer<<<blocks, 256, smem>>>(gbuf, edge + eoff, timef + toff,
                                     W1 + D1 * DD, b1 + DD,
                                     W2 + 2 * DD * DD, b2 + DD,
                                     idx, 1, out, N);
}

// round 16
// speedup vs baseline: 1.3408x; 1.2682x over previous
#include <cuda_runtime.h>
#include <cstdint>

// ---------------------------------------------------------------------------
// TGN layer-graph sum embedding. Round 16: registerized B operand.
// R15 insight: cp.async W staging has ~zero smem reuse (each W element feeds
// only 2 warps/CTA) yet costs ~43us ldgsts + ~40us LDS + 17KB smem + ~28
// barriers per CTA per layer, doubled by the 4-CTA occupancy win.
// R16: a prepass kernel repacks W (both layers) into fragment-ordered,
// pre-tf32-converted float4s in a __device__ scratch. GEMMs read B straight
// from global (LDG.128, 2-step register double buffer, L2/L1-hot across all
// CTAs). No Ws smem, no cp.async, no in-GEMM barriers (5 barriers/layer vs
// ~31), no in-loop B cvt. Warp tile 32x16 (B read exactly once per CTA).
// Phase A / reload / idx detection unchanged from R15. TB=32, 4 CTAs/SM.
// ---------------------------------------------------------------------------

#define DD   128
#define KK   16
#define DE   32
#define DT   32
#define D1   192
#define TB   32
#define PA_  196            // agg pitch (floats), 196 % 32 == 4
#define NMAX 100000

#define NSTEP1 24           // W1 k8 steps (192/8)
#define NSTEP2 32           // W2 k8 steps (256/8)
#define MSZ1 (NSTEP1*1024)  // floats per repacked W1 (24*8*32*4)
#define MSZ2 (NSTEP2*1024)
#define LOFF (MSZ1+MSZ2)    // 57344 floats per layer

__device__ float g_buf[(size_t)NMAX * DD];   // layer-0 output ping buffer
__device__ float g_wbuf[2 * LOFF];           // repacked tf32 W, both layers

__device__ __forceinline__ uint32_t f2tf(float x) {
    uint32_t r; asm("cvt.rna.tf32.f32 %0, %1;" : "=r"(r) : "f"(x)); return r;
}
__device__ __forceinline__ void mma_tf32(float d[4], const uint32_t a[4], const uint32_t b[2]) {
    asm volatile(
        "mma.sync.aligned.m16n8k8.row.col.f32.tf32.tf32.f32 "
        "{%0,%1,%2,%3}, {%4,%5,%6,%7}, {%8,%9}, {%0,%1,%2,%3};"
        : "+f"(d[0]), "+f"(d[1]), "+f"(d[2]), "+f"(d[3])
        : "r"(a[0]), "r"(a[1]), "r"(a[2]), "r"(a[3]), "r"(b[0]), "r"(b[1]));
}

// ---- prepass: repack W into fragment-ordered tf32 float4s ------------------
// Per k8-step s, col-group ng (16 cols), lane (gid=lane>>2 col, tig=lane&3 k):
//   v = { W[8s+tig][16ng+gid], W[8s+tig+4][16ng+gid],
//         W[8s+tig][16ng+8+gid], W[8s+tig+4][16ng+8+gid] }  (tf32 bits)
__global__ void prep_w(const float* __restrict__ W1, const float* __restrict__ W2) {
    int b = blockIdx.x, tid = threadIdx.x;
    int ng = tid >> 5, lane = tid & 31;
    int gid = lane >> 2, tig = lane & 3;
    const float* src; float* dst; int s;
    if (b < NSTEP1)                    { src = W1;             dst = g_wbuf;               s = b; }
    else if (b < NSTEP1 + NSTEP2)      { src = W2;             dst = g_wbuf + MSZ1;        s = b - NSTEP1; }
    else if (b < 2*NSTEP1 + NSTEP2)    { src = W1 + D1 * DD;   dst = g_wbuf + LOFF;        s = b - (NSTEP1 + NSTEP2); }
    else                               { src = W2 + 2*DD*DD;   dst = g_wbuf + LOFF + MSZ1; s = b - (2*NSTEP1 + NSTEP2); }
    int col = 16 * ng + gid;
    const float* p0 = src + (size_t)(8 * s + tig) * DD;
    float4 v;
    v.x = __uint_as_float(f2tf(p0[col]));
    v.y = __uint_as_float(f2tf(p0[4 * DD + col]));
    v.z = __uint_as_float(f2tf(p0[col + 8]));
    v.w = __uint_as_float(f2tf(p0[4 * DD + col + 8]));
    ((float4*)dst)[(s * 8 + ng) * 32 + lane] = v;
}

// ---- GEMM: acc[2 mi][2 ni][4] += A(32 x 8*nSteps, smem) @ Bpre --------------
// Warp w owns cols [16w,16w+16), rows 0..31. B via LDG.128, 2-step prefetch.
// NO barriers inside; caller syncs around agg writes. nSteps even.
__device__ __forceinline__ void gemm_reg(
    const float* __restrict__ Ag,
    const float4* __restrict__ Bp,       // + w*32 + lane applied inside
    int nSteps, float acc[2][2][4],
    int gid, int tig, int wln)           // wln = w*32 + lane
{
    const float4* bp = Bp + wln;
    float4 nb0 = bp[0];
    float4 nb1 = bp[256];
    for (int s = 0; s < nSteps; s += 2) {
        float4 b0 = nb0, b1 = nb1;
        if (s + 2 < nSteps) nb0 = bp[(size_t)(s + 2) * 256];
        if (s + 3 < nSteps) nb1 = bp[(size_t)(s + 3) * 256];

        // step s
        {
            uint32_t bf0[2] = { __float_as_uint(b0.x), __float_as_uint(b0.y) };
            uint32_t bf1[2] = { __float_as_uint(b0.z), __float_as_uint(b0.w) };
            const float* ap0 = Ag + gid * PA_ + 8 * s + tig;
            #pragma unroll
            for (int mi = 0; mi < 2; mi++) {
                const float* ap = ap0 + mi * 16 * PA_;
                uint32_t af[4];
                af[0] = f2tf(ap[0]);
                af[1] = f2tf(ap[8 * PA_]);
                af[2] = f2tf(ap[4]);
                af[3] = f2tf(ap[8 * PA_ + 4]);
                mma_tf32(acc[mi][0], af, bf0);
                mma_tf32(acc[mi][1], af, bf1);
            }
        }
        // step s+1
        {
            uint32_t bf0[2] = { __float_as_uint(b1.x), __float_as_uint(b1.y) };
            uint32_t bf1[2] = { __float_as_uint(b1.z), __float_as_uint(b1.w) };
            const float* ap0 = Ag + gid * PA_ + 8 * (s + 1) + tig;
            #pragma unroll
            for (int mi = 0; mi < 2; mi++) {
                const float* ap = ap0 + mi * 16 * PA_;
                uint32_t af[4];
                af[0] = f2tf(ap[0]);
                af[1] = f2tf(ap[8 * PA_]);
                af[2] = f2tf(ap[4]);
                af[3] = f2tf(ap[8 * PA_ + 4]);
                mma_tf32(acc[mi][0], af, bf0);
                mma_tf32(acc[mi][1], af, bf1);
            }
        }
    }
}

extern "C" __global__ void __launch_bounds__(256, 4)
tgn_layer(const float* __restrict__ src,
          const float* __restrict__ e,
          const float* __restrict__ t,
          const float* __restrict__ bpre,    // g_wbuf + layer*LOFF
          const float* __restrict__ b1g,
          const float* __restrict__ b2g,
          const void* __restrict__ idxRaw,
          int layer,
          float* __restrict__ dst,
          int N)
{
    extern __shared__ float sm[];
    float* agg = sm;                  // [32][PA_] row-major; cols 0..127 reused
    __shared__ int s_flag;

    const int tid  = threadIdx.x;
    const int lane = tid & 31;
    const int w    = tid >> 5;
    const int gid  = lane >> 2;       // 0..7
    const int tig  = lane & 3;        // 0..3
    const int wln  = w * 32 + lane;
    const int base = blockIdx.x * TB;

    // idx dtype detection (int64 values < 1e5 -> every odd 32-bit word == 0)
    if (tid == 0) s_flag = 0;
    __syncthreads();
    if (tid < 64) {
        int v = ((const int*)idxRaw)[2 * tid + 1];
        if (v != 0) atomicOr(&s_flag, 1);
    }
    __syncthreads();
    const int idx64 = (s_flag == 0);

    const long long* i64 = (const long long*)idxRaw + (size_t)layer * N * KK;
    const int*       i32 = (const int*)idxRaw       + (size_t)layer * N * KK;

    // ---------------- Phase A: aggregation -> row-major smem ----------------
    #pragma unroll 1
    for (int i = 0; i < 4; i++) {
        int ln = w * 4 + i;
        int n  = base + ln;
        if (n >= N) continue;     // warp-uniform
        float4 accA = {0.f,0.f,0.f,0.f}, accB = {0.f,0.f,0.f,0.f};
        float es = 0.f, ts = 0.f;

        #pragma unroll
        for (int jj = 0; jj < 4; jj++) {
            long long q0, q1, q2, q3;
            if (idx64) {
                const long long* p = i64 + (size_t)n * KK + jj * 4;
                q0 = p[0]; q1 = p[1]; q2 = p[2]; q3 = p[3];
            } else {
                int4 v = ((const int4*)(i32 + (size_t)n * KK))[jj];
                q0 = v.x; q1 = v.y; q2 = v.z; q3 = v.w;
            }
            float4 v0 = ((const float4*)(src + (size_t)q0 * DD))[lane];
            float4 v1 = ((const float4*)(src + (size_t)q1 * DD))[lane];
            float4 v2 = ((const float4*)(src + (size_t)q2 * DD))[lane];
            float4 v3 = ((const float4*)(src + (size_t)q3 * DD))[lane];
            accA.x += v0.x; accA.y += v0.y; accA.z += v0.z; accA.w += v0.w;
            accB.x += v1.x; accB.y += v1.y; accB.z += v1.z; accB.w += v1.w;
            accA.x += v2.x; accA.y += v2.y; accA.z += v2.z; accA.w += v2.w;
            accB.x += v3.x; accB.y += v3.y; accB.z += v3.z; accB.w += v3.w;
        }
        const float* ep = e + (size_t)n * (KK * DE);
        const float* tp = t + (size_t)n * (KK * DT);
        #pragma unroll
        for (int j = 0; j < KK; j++) {
            es += ep[j * DE + lane];
            ts += tp[j * DT + lane];
        }
        accA.x += accB.x; accA.y += accB.y; accA.z += accB.z; accA.w += accB.w;

        *(float4*)&agg[ln * PA_ + 4 * lane] = accA;   // conflict-free STS.128
        agg[ln * PA_ + DD + lane]      = es;
        agg[ln * PA_ + DD + DE + lane] = ts;
    }
    __syncthreads();

    // ---------------- Phase B: h = relu(agg @ W1 + b1) ----------------------
    float acc[2][2][4];
    #pragma unroll
    for (int mi = 0; mi < 2; mi++)
        #pragma unroll
        for (int ni = 0; ni < 2; ni++)
            #pragma unroll
            for (int q = 0; q < 4; q++) acc[mi][ni][q] = 0.f;

    gemm_reg(agg, (const float4*)bpre, NSTEP1, acc, gid, tig, wln);
    __syncthreads();   // all warps done reading agg before h overwrites

    #pragma unroll
    for (int mi = 0; mi < 2; mi++)
        #pragma unroll
        for (int ni = 0; ni < 2; ni++) {
            int row = 16 * mi + gid;
            int col = 16 * w + 8 * ni + 2 * tig;
            float bv0 = b1g[col], bv1 = b1g[col + 1];
            float2 lo = { fmaxf(acc[mi][ni][0] + bv0, 0.f),
                          fmaxf(acc[mi][ni][1] + bv1, 0.f) };
            float2 hi = { fmaxf(acc[mi][ni][2] + bv0, 0.f),
                          fmaxf(acc[mi][ni][3] + bv1, 0.f) };
            *(float2*)&agg[row * PA_ + col]       = lo;
            *(float2*)&agg[(row + 8) * PA_ + col] = hi;
            #pragma unroll
            for (int q = 0; q < 4; q++) acc[mi][ni][q] = 0.f;
        }
    __syncthreads();   // h visible before C1 reads

    // ---------------- Phase C1: acc += h @ W2[128:256] ----------------------
    gemm_reg(agg, (const float4*)(bpre + MSZ1) + 16 * 256, 16, acc, gid, tig, wln);
    __syncthreads();   // C1 reads done before reload overwrites

    // ---------------- reload own rows (L2-hot) into agg cols 0..127 ---------
    {
        const float4* cp4 = (const float4*)(src + (size_t)base * DD);
        #pragma unroll
        for (int i = 0; i < 4; i++) {
            int f  = tid + 256 * i;      // 0..1023
            int n  = f >> 5;             // node 0..31
            int k4 = f & 31;
            if (base + n < N)
                *(float4*)&agg[n * PA_ + 4 * k4] = cp4[f];
        }
    }
    __syncthreads();   // reload visible before C2 reads

    // ---------------- Phase C2: acc += cur @ W2[0:128] ----------------------
    gemm_reg(agg, (const float4*)(bpre + MSZ1), 16, acc, gid, tig, wln);

    #pragma unroll
    for (int mi = 0; mi < 2; mi++)
        #pragma unroll
        for (int ni = 0; ni < 2; ni++) {
            int row = 16 * mi + gid;
            int col = 16 * w + 8 * ni + 2 * tig;
            float bv0 = b2g[col], bv1 = b2g[col + 1];
            int n1 = base + row, n2 = base + row + 8;
            if (n1 < N) {
                float2 o = { acc[mi][ni][0] + bv0, acc[mi][ni][1] + bv1 };
                *(float2*)&dst[(size_t)n1 * DD + col] = o;
            }
            if (n2 < N) {
                float2 o = { acc[mi][ni][2] + bv0, acc[mi][ni][3] + bv1 };
                *(float2*)&dst[(size_t)n2 * DD + col] = o;
            }
        }
}

extern "C" void kernel_launch(void* const* d_in, const int* in_sizes, int n_in,
                              void* d_out, int out_size)
{
    const float* features = (const float*)d_in[0];
    const float* edge     = (const float*)d_in[1];
    const float* timef    = (const float*)d_in[2];
    const float* W1       = (const float*)d_in[3];
    const float* b1       = (const float*)d_in[4];
    const float* W2       = (const float*)d_in[5];
    const float* b2       = (const float*)d_in[6];
    const void*  idx      = d_in[7];
    float*       out      = (float*)d_out;

    const int N = in_sizes[0] / DD;

    const size_t smem = (size_t)(TB * PA_) * sizeof(float);   // 25,088 B
    cudaFuncSetAttribute(tgn_layer, cudaFuncAttributeMaxDynamicSharedMemorySize, (int)smem);

    void* gptr = nullptr;
    cudaGetSymbolAddress(&gptr, g_buf);
    float* gbuf = (float*)gptr;
    void* wptr = nullptr;
    cudaGetSymbolAddress(&wptr, g_wbuf);
    float* wbuf = (float*)wptr;

    const int blocks = (N + TB - 1) / TB;
    const size_t eoff = (size_t)N * KK * DE;
    const size_t toff = (size_t)N * KK * DT;

    // repack W (both layers) into fragment-ordered tf32
    prep_w<<<2 * (NSTEP1 + NSTEP2), 256>>>(W1, W2);

    tgn_layer<<<blocks, 256, smem>>>(features, edge, timef,
                                     wbuf, b1, b2, idx, 0, gbuf, N);
    tgn_layer<<<blocks, 256, smem>>>(gbuf, edge + eoff, timef + toff,
                                     wbuf + LOFF, b1 + DD, b2 + DD,
                                     idx, 1, out, N);
}